// round 17
// baseline (speedup 1.0000x reference)
#include <cuda_runtime.h>
#include <cstdint>

#define NG      16
#define WARPSZ  32
#define NWARPS  4
#define TPB     (NWARPS * WARPSZ)
#define ITERS   4
// per-warp buffer: 1024 floats means + 1024 floats covs = 2048 floats = 8 KB
#define BUF_FLOATS   2048
#define WARP_FLOATS  (2 * BUF_FLOATS)          // double buffer
#define SMEM_FLOATS  (NWARPS * WARP_FLOATS)    // 16384 floats = 64 KB
#define SMEM_BYTES   (SMEM_FLOATS * 4)

// 64 * log(2*pi)
#define D_LOG_2PI 117.6241322f

__device__ __forceinline__ void prefetch_row(
    float* dst, const float4* means, const float4* covs, size_t b, int lane)
{
    const float4* mp = means + b * 256;
    const float4* cp = covs  + b * 256;
    #pragma unroll
    for (int c = 0; c < 8; c++) {
        const int o = c * 32 + lane;               // float4 index within row
        uint32_t smu = (uint32_t)__cvta_generic_to_shared(dst + o * 4);
        asm volatile("cp.async.cg.shared.global [%0], [%1], 16;\n"
                     :: "r"(smu), "l"(mp + o));
        uint32_t svv = (uint32_t)__cvta_generic_to_shared(dst + 1024 + o * 4);
        asm volatile("cp.async.cg.shared.global [%0], [%1], 16;\n"
                     :: "r"(svv), "l"(cp + o));
    }
    asm volatile("cp.async.commit_group;\n");
}

__global__ void __launch_bounds__(TPB) gmm_loss_kernel(
    const float4* __restrict__ means,
    const float4* __restrict__ covs,
    const float*  __restrict__ weights,
    const float4* __restrict__ targets,
    float* __restrict__ out)
{
    extern __shared__ float smem[];

    const int warp = threadIdx.x >> 5;
    const int lane = threadIdx.x & 31;
    float* wbuf = smem + warp * WARP_FLOATS;

    const int s    = lane & 15;   // sub-lane within 16-lane half
    const int half = lane >> 4;   // 0: even gaussians, 1: odd gaussians

    // This lane's final gaussian after folding: value v = 4*b1 + 2*b2 + b3.
    const int vidx = ((s >> 1) & 1) * 4 + ((s >> 2) & 1) * 2 + ((s >> 3) & 1);
    const int g    = 2 * vidx + half;

    const bool b3 = (s & 8) != 0;
    const bool b2 = (s & 4) != 0;
    const bool b1 = (s & 2) != 0;

    // Each warp owns ITERS consecutive rows.
    const size_t b0 = (size_t)(blockIdx.x * NWARPS + warp) * ITERS;

    // Prologue: prefetch rows 0 and 1; stage their target/weight in regs.
    float4 t4r[2];
    float  wtr[2];
    prefetch_row(wbuf,              means, covs, b0,     lane);
    t4r[0] = targets[b0 * 16 + s];
    wtr[0] = __ldg(weights + b0 * NG + g);
    prefetch_row(wbuf + BUF_FLOATS, means, covs, b0 + 1, lane);
    t4r[1] = targets[(b0 + 1) * 16 + s];
    wtr[1] = __ldg(weights + (b0 + 1) * NG + g);

    #pragma unroll
    for (int it = 0; it < ITERS; it++) {
        // Wait until this iteration's buffer (oldest pending group) has landed.
        if (it + 1 < ITERS) asm volatile("cp.async.wait_group 1;\n");
        else                asm volatile("cp.async.wait_group 0;\n");

        const float* buf = wbuf + (it & 1) * BUF_FLOATS;
        const float4 t4  = t4r[it & 1];
        const float  wt  = wtr[it & 1];

        // Per-chunk fused partial: h[c] = sum(e^2/v) + sum(log v) over 4 dims.
        // Layout: means at buf[0..1023], covs at buf[1024..2047].
        float h[8];
        #pragma unroll
        for (int c = 0; c < 8; c++) {
            const int o = (c * 32 + lane) * 4;
            const float4 m4 = *reinterpret_cast<const float4*>(buf + o);
            const float4 v4 = *reinterpret_cast<const float4*>(buf + 1024 + o);
            const float e0 = t4.x - m4.x;
            const float e1 = t4.y - m4.y;
            const float e2 = t4.z - m4.z;
            const float e3 = t4.w - m4.w;
            const float p01 = v4.x * v4.y;
            const float p23 = v4.z * v4.w;
            const float P   = p01 * p23;
            float num = (e0 * e0) * (v4.y * p23);
            num = fmaf(e1 * e1, v4.x * p23, num);
            num = fmaf(e2 * e2, v4.w * p01, num);
            num = fmaf(e3 * e3, v4.z * p01, num);
            h[c] = __fdividef(num, P) + __logf(P);
        }

        // Prefetch row it+2 into the buffer we just finished reading.
        // Safe without sync: each lane reads/writes only its own addresses.
        if (it + 2 < ITERS) {
            const size_t bn = b0 + it + 2;
            prefetch_row(wbuf + (it & 1) * BUF_FLOATS, means, covs, bn, lane);
            t4r[it & 1] = targets[bn * 16 + s];
            wtr[it & 1] = __ldg(weights + bn * NG + g);
        }

        // ---- Value-lane folding: 8 values over 16 lanes, single quantity ----
        float a[4];
        #pragma unroll
        for (int k = 0; k < 4; k++) {
            float kv = b3 ? h[2*k+1] : h[2*k];
            float sv = b3 ? h[2*k]   : h[2*k+1];
            a[k] = kv + __shfl_xor_sync(0xffffffffu, sv, 8);
        }
        float u[2];
        #pragma unroll
        for (int j = 0; j < 2; j++) {
            float kv = b2 ? a[2*j+1] : a[2*j];
            float sv = b2 ? a[2*j]   : a[2*j+1];
            u[j] = kv + __shfl_xor_sync(0xffffffffu, sv, 4);
        }
        float kv = b1 ? u[1] : u[0];
        float sv = b1 ? u[0] : u[1];
        float w  = kv + __shfl_xor_sync(0xffffffffu, sv, 2);
        w += __shfl_xor_sync(0xffffffffu, w, 1);

        // ---- Epilogue: all 32 lanes finish their gaussian in parallel ----
        float lp = -0.5f * (D_LOG_2PI + w);     // w = logdet + quad
        lp = fminf(fmaxf(lp, -100.0f), 0.0f);
        lp += __logf(wt);

        // logsumexp over offsets {2,4,8,16}: bit0 is the duplicate axis.
        float m = lp;
        m = fmaxf(m, __shfl_xor_sync(0xffffffffu, m, 2));
        m = fmaxf(m, __shfl_xor_sync(0xffffffffu, m, 4));
        m = fmaxf(m, __shfl_xor_sync(0xffffffffu, m, 8));
        m = fmaxf(m, __shfl_xor_sync(0xffffffffu, m, 16));

        float e = __expf(lp - m);
        e += __shfl_xor_sync(0xffffffffu, e, 2);
        e += __shfl_xor_sync(0xffffffffu, e, 4);
        e += __shfl_xor_sync(0xffffffffu, e, 8);
        e += __shfl_xor_sync(0xffffffffu, e, 16);

        if (lane == 0)
            out[b0 + it] = -(m + __logf(e));
    }
}

extern "C" void kernel_launch(void* const* d_in, const int* in_sizes, int n_in,
                              void* d_out, int out_size)
{
    const float4* means   = (const float4*)d_in[0];
    const float4* covs    = (const float4*)d_in[1];
    const float*  weights = (const float*)d_in[2];
    const float4* targets = (const float4*)d_in[3];
    float*        out     = (float*)d_out;

    const int B = in_sizes[2] / NG;   // weights has B*16 elements

    cudaFuncSetAttribute(gmm_loss_kernel,
                         cudaFuncAttributeMaxDynamicSharedMemorySize,
                         SMEM_BYTES);

    const int grid = B / (NWARPS * ITERS);
    gmm_loss_kernel<<<grid, TPB, SMEM_BYTES>>>(means, covs, weights, targets, out);
}